// round 4
// baseline (speedup 1.0000x reference)
#include <cuda_runtime.h>
#include <cuda_bf16.h>

#define N_NODES 50000
#define N_EDGES 800000
#define DIM 128

// ---------------- scratch (static __device__ arrays; no allocation) ----------
__device__ int   g_deg[N_NODES];
__device__ float g_dinv[N_NODES];
__device__ int   g_rowptr[N_NODES + 1];
__device__ int   g_cursor[N_NODES];
__device__ int   g_csrsrc[N_EDGES];
__device__ float g_csrw[N_EDGES];
__device__ float g_bufA[(size_t)N_NODES * DIM];  // GEMM outputs
__device__ float g_bufB[(size_t)N_NODES * DIM];  // h1

// packed fp32x2 FMA: {d0,d1} += {a0,a1} * {b0,b1}
__device__ __forceinline__ void ffma2(float& d0, float& d1,
                                      float a0, float a1,
                                      float b0, float b1) {
    asm("{\n\t"
        ".reg .b64 ra, rb, rc;\n\t"
        "mov.b64 ra, {%2, %3};\n\t"
        "mov.b64 rb, {%4, %5};\n\t"
        "mov.b64 rc, {%0, %1};\n\t"
        "fma.rn.f32x2 rc, ra, rb, rc;\n\t"
        "mov.b64 {%0, %1}, rc;\n\t"
        "}"
        : "+f"(d0), "+f"(d1)
        : "f"(a0), "f"(a1), "f"(b0), "f"(b1));
}

// ---------------- graph preprocessing ----------------------------------------
__global__ void init_deg_kernel() {
    int i = blockIdx.x * blockDim.x + threadIdx.x;
    if (i < N_NODES) g_deg[i] = 1;  // self-loop
}

// edge_index is int32 (JAX x64-disabled downcasts the declared int64)
__global__ void count_kernel(const int* __restrict__ ei) {
    int e = blockIdx.x * blockDim.x + threadIdx.x;
    if (e < N_EDGES) {
        unsigned d = (unsigned)ei[N_EDGES + e];
        if (d < N_NODES) atomicAdd(&g_deg[d], 1);
    }
}

// single-block exclusive scan over edge counts (deg-1); also fills dinv + cursor
__global__ void scan_kernel() {
    __shared__ int s[1024];
    const int t = threadIdx.x;
    const int CH = (N_NODES + 1023) / 1024;  // 49
    int start = t * CH;
    int end = start + CH; if (end > N_NODES) end = N_NODES;
    int sum = 0;
    for (int i = start; i < end; i++) sum += g_deg[i] - 1;
    s[t] = sum;
    __syncthreads();
    for (int off = 1; off < 1024; off <<= 1) {
        int v = 0;
        if (t >= off) v = s[t - off];
        __syncthreads();
        if (t >= off) s[t] += v;
        __syncthreads();
    }
    int run = (t == 0) ? 0 : s[t - 1];
    for (int i = start; i < end; i++) {
        g_rowptr[i] = run;
        run += g_deg[i] - 1;
        g_cursor[i] = 0;
        g_dinv[i] = rsqrtf((float)g_deg[i]);
    }
    if (t == 1023) g_rowptr[N_NODES] = s[1023];
}

__global__ void scatter_kernel(const int* __restrict__ ei) {
    int e = blockIdx.x * blockDim.x + threadIdx.x;
    if (e < N_EDGES) {
        unsigned src = (unsigned)ei[e];
        unsigned dst = (unsigned)ei[N_EDGES + e];
        if (src < N_NODES && dst < N_NODES) {
            int pos = g_rowptr[dst] + atomicAdd(&g_cursor[dst], 1);
            g_csrsrc[pos] = src;
            g_csrw[pos] = g_dinv[src] * g_dinv[dst];
        }
    }
}

// ---------------- GEMM: C[M,128] = A[M,128] * W[128,128] (+bias) --------------
// 256 threads/block, 64 rows/block, each thread computes 8 rows x 4 cols.
// Inner loop: k-pairs with packed fma.rn.f32x2 (2 FMAs/instr -> 2x fp32 rate).
// SRC_BUF: 0 = read from param A, 1 = read from g_bufB
// DST: 0 = write g_bufA, 1 = write param C
template <int SRC_BUF, int DST, bool ADD_BIAS>
__global__ void __launch_bounds__(256, 2)
gemm128_kernel(const float* __restrict__ A,
               const float* __restrict__ W,
               const float* __restrict__ bias,
               float* __restrict__ C, int M) {
    __shared__ float as[64][DIM];
    const int tx = threadIdx.x & 31;   // col group: cols 4*tx..4*tx+3
    const int ty = threadIdx.x >> 5;   // row group 0..7
    const int row0 = blockIdx.x * 64;

    const float4* A4 = SRC_BUF ? (const float4*)g_bufB : (const float4*)A;
    for (int i = threadIdx.x; i < 64 * 32; i += 256) {
        int r = i >> 5, c = i & 31;
        float4 v = make_float4(0.f, 0.f, 0.f, 0.f);
        if (row0 + r < M) v = A4[(size_t)(row0 + r) * 32 + c];
        ((float4*)as[r])[c] = v;
    }
    __syncthreads();

    // acc[r][c]: .x = even-k partial, .y = odd-k partial
    float2 acc[8][4];
#pragma unroll
    for (int r = 0; r < 8; r++)
#pragma unroll
        for (int c = 0; c < 4; c++) acc[r][c] = make_float2(0.f, 0.f);

    const float4* W4 = (const float4*)W;
#pragma unroll 4
    for (int k = 0; k < DIM; k += 2) {
        float4 wE = __ldg(&W4[(k + 0) * 32 + tx]);
        float4 wO = __ldg(&W4[(k + 1) * 32 + tx]);
#pragma unroll
        for (int r = 0; r < 8; r++) {
            float2 a2 = *(const float2*)&as[ty * 8 + r][k];
            ffma2(acc[r][0].x, acc[r][0].y, a2.x, a2.y, wE.x, wO.x);
            ffma2(acc[r][1].x, acc[r][1].y, a2.x, a2.y, wE.y, wO.y);
            ffma2(acc[r][2].x, acc[r][2].y, a2.x, a2.y, wE.z, wO.z);
            ffma2(acc[r][3].x, acc[r][3].y, a2.x, a2.y, wE.w, wO.w);
        }
    }

    float4 bv = make_float4(0.f, 0.f, 0.f, 0.f);
    if (ADD_BIAS) bv = ((const float4*)bias)[tx];
    float4* Cout = DST ? (float4*)C : (float4*)g_bufA;
#pragma unroll
    for (int r = 0; r < 8; r++) {
        int row = row0 + ty * 8 + r;
        if (row < M) {
            float4 o;
            o.x = acc[r][0].x + acc[r][0].y;
            o.y = acc[r][1].x + acc[r][1].y;
            o.z = acc[r][2].x + acc[r][2].y;
            o.w = acc[r][3].x + acc[r][3].y;
            if (ADD_BIAS) { o.x += bv.x; o.y += bv.y; o.z += bv.z; o.w += bv.w; }
            Cout[(size_t)row * 32 + tx] = o;
        }
    }
}

// ---------------- aggregation: out[i] = sum_j norm*h[src] + self + bias -------
// reads g_bufA; DST_BUF: 1 = write g_bufB, 0 = write param out
// block = (32,8): 32 lanes (float4 over 128 feats) x 8 nodes per block
template <int DST_BUF, bool RELU>
__global__ void aggregate_kernel(const float* __restrict__ bias,
                                 float* __restrict__ out) {
    int node = blockIdx.x * 8 + threadIdx.y;
    if (node >= N_NODES) return;
    int lane = threadIdx.x;

    const float4* H4 = (const float4*)g_bufA;
    float di = g_dinv[node];
    float w0 = di * di;
    float4 h = H4[(size_t)node * 32 + lane];
    float4 acc = make_float4(h.x * w0, h.y * w0, h.z * w0, h.w * w0);

    int beg = g_rowptr[node];
    int end = g_rowptr[node + 1];
    int j = beg;
    // 2-wide unroll for MLP against L2 latency
    for (; j + 1 < end; j += 2) {
        int s0 = g_csrsrc[j];
        int s1 = g_csrsrc[j + 1];
        float wa = g_csrw[j];
        float wb = g_csrw[j + 1];
        float4 v0 = H4[(size_t)s0 * 32 + lane];
        float4 v1 = H4[(size_t)s1 * 32 + lane];
        acc.x += v0.x * wa; acc.y += v0.y * wa;
        acc.z += v0.z * wa; acc.w += v0.w * wa;
        acc.x += v1.x * wb; acc.y += v1.y * wb;
        acc.z += v1.z * wb; acc.w += v1.w * wb;
    }
    if (j < end) {
        int s = g_csrsrc[j];
        float w = g_csrw[j];
        float4 v = H4[(size_t)s * 32 + lane];
        acc.x += v.x * w; acc.y += v.y * w;
        acc.z += v.z * w; acc.w += v.w * w;
    }

    float4 bv = ((const float4*)bias)[lane];
    acc.x += bv.x; acc.y += bv.y; acc.z += bv.z; acc.w += bv.w;
    if (RELU) {
        acc.x = fmaxf(acc.x, 0.f);
        acc.y = fmaxf(acc.y, 0.f);
        acc.z = fmaxf(acc.z, 0.f);
        acc.w = fmaxf(acc.w, 0.f);
    }
    float4* O = DST_BUF ? (float4*)g_bufB : (float4*)out;
    O[(size_t)node * 32 + lane] = acc;
}

// ---------------- launch ------------------------------------------------------
extern "C" void kernel_launch(void* const* d_in, const int* in_sizes, int n_in,
                              void* d_out, int out_size) {
    const float* x    = (const float*)d_in[0];
    const int*   ei   = (const int*)d_in[1];
    const float* qemb = (const float*)d_in[2];
    const float* W1   = (const float*)d_in[3];
    const float* b1   = (const float*)d_in[4];
    const float* W2   = (const float*)d_in[5];
    const float* b2   = (const float*)d_in[6];
    const float* Wq   = (const float*)d_in[7];
    const float* bq   = (const float*)d_in[8];

    float* out = (float*)d_out;
    float* out_ques = out;                          // [20000,128]
    float* out_h2   = out + (size_t)20000 * DIM;    // [50000,128]

    // graph preprocessing (CSR build, shared by both layers)
    init_deg_kernel<<<(N_NODES + 255) / 256, 256>>>();
    count_kernel<<<(N_EDGES + 255) / 256, 256>>>(ei);
    scan_kernel<<<1, 1024>>>();
    scatter_kernel<<<(N_EDGES + 255) / 256, 256>>>(ei);

    const int gblk = 256;
    // layer 1: g_bufA = x @ W1 ; g_bufB = relu(agg(g_bufA) + b1)
    gemm128_kernel<0, 0, false><<<(N_NODES + 63) / 64, gblk>>>(x, W1, nullptr, nullptr, N_NODES);
    aggregate_kernel<1, true><<<(N_NODES + 7) / 8, dim3(32, 8)>>>(b1, nullptr);
    // layer 2: g_bufA = g_bufB @ W2 ; out_h2 = agg(g_bufA) + b2
    gemm128_kernel<1, 0, false><<<(N_NODES + 63) / 64, gblk>>>(nullptr, W2, nullptr, nullptr, N_NODES);
    aggregate_kernel<0, false><<<(N_NODES + 7) / 8, dim3(32, 8)>>>(b2, out_h2);
    // question path: ques = q_emb @ Wq + bq
    gemm128_kernel<0, 1, true><<<(20000 + 63) / 64, gblk>>>(qemb, Wq, bq, out_ques, 20000);
}

// round 5
// speedup vs baseline: 1.0929x; 1.0929x over previous
#include <cuda_runtime.h>
#include <cuda_bf16.h>

#define N_NODES 50000
#define N_EDGES 800000
#define DIM 128

// ---------------- scratch (static __device__ arrays; no allocation) ----------
__device__ int   g_deg[N_NODES];
__device__ float g_dinv[N_NODES];
__device__ int   g_rowptr[N_NODES + 1];
__device__ int   g_cursor[N_NODES];
__device__ int   g_csrsrc[N_EDGES];
__device__ float g_csrw[N_EDGES];
__device__ float g_bufA[(size_t)N_NODES * DIM];  // GEMM outputs
__device__ float g_bufB[(size_t)N_NODES * DIM];  // h1
// pair-interleaved weights: Wp[k2*DIM + c] = (W[2k2][c], W[2k2+1][c])
__device__ float2 g_W1p[64 * DIM];
__device__ float2 g_W2p[64 * DIM];
__device__ float2 g_Wqp[64 * DIM];

// pure packed fp32x2 FMA: acc(pair) += a(pair) * b(pair), no marshalling movs
__device__ __forceinline__ void ffma2p(unsigned long long& acc,
                                       unsigned long long a,
                                       unsigned long long b) {
    asm("fma.rn.f32x2 %0, %1, %2, %0;" : "+l"(acc) : "l"(a), "l"(b));
}

// ---------------- weight pre-packing ------------------------------------------
__global__ void pack_w_kernel(const float* __restrict__ W1,
                              const float* __restrict__ W2,
                              const float* __restrict__ Wq) {
    int i = blockIdx.x * blockDim.x + threadIdx.x;  // 0 .. 64*128-1
    if (i >= 64 * DIM) return;
    int k2 = i / DIM, c = i % DIM;
    g_W1p[i] = make_float2(W1[(2 * k2) * DIM + c], W1[(2 * k2 + 1) * DIM + c]);
    g_W2p[i] = make_float2(W2[(2 * k2) * DIM + c], W2[(2 * k2 + 1) * DIM + c]);
    g_Wqp[i] = make_float2(Wq[(2 * k2) * DIM + c], Wq[(2 * k2 + 1) * DIM + c]);
}

// ---------------- graph preprocessing ----------------------------------------
__global__ void init_deg_kernel() {
    int i = blockIdx.x * blockDim.x + threadIdx.x;
    if (i < N_NODES) g_deg[i] = 1;  // self-loop
}

// edge_index is int32 (JAX x64-disabled downcasts the declared int64)
__global__ void count_kernel(const int* __restrict__ ei) {
    int e = blockIdx.x * blockDim.x + threadIdx.x;
    if (e < N_EDGES) {
        unsigned d = (unsigned)ei[N_EDGES + e];
        if (d < N_NODES) atomicAdd(&g_deg[d], 1);
    }
}

// single-block exclusive scan over edge counts (deg-1); also fills dinv + cursor
__global__ void scan_kernel() {
    __shared__ int s[1024];
    const int t = threadIdx.x;
    const int CH = (N_NODES + 1023) / 1024;  // 49
    int start = t * CH;
    int end = start + CH; if (end > N_NODES) end = N_NODES;
    int sum = 0;
    for (int i = start; i < end; i++) sum += g_deg[i] - 1;
    s[t] = sum;
    __syncthreads();
    for (int off = 1; off < 1024; off <<= 1) {
        int v = 0;
        if (t >= off) v = s[t - off];
        __syncthreads();
        if (t >= off) s[t] += v;
        __syncthreads();
    }
    int run = (t == 0) ? 0 : s[t - 1];
    for (int i = start; i < end; i++) {
        g_rowptr[i] = run;
        run += g_deg[i] - 1;
        g_cursor[i] = 0;
        g_dinv[i] = rsqrtf((float)g_deg[i]);
    }
    if (t == 1023) g_rowptr[N_NODES] = s[1023];
}

__global__ void scatter_kernel(const int* __restrict__ ei) {
    int e = blockIdx.x * blockDim.x + threadIdx.x;
    if (e < N_EDGES) {
        unsigned src = (unsigned)ei[e];
        unsigned dst = (unsigned)ei[N_EDGES + e];
        if (src < N_NODES && dst < N_NODES) {
            int pos = g_rowptr[dst] + atomicAdd(&g_cursor[dst], 1);
            g_csrsrc[pos] = src;
            g_csrw[pos] = g_dinv[src] * g_dinv[dst];
        }
    }
}

// ---------------- GEMM: C[M,128] = A[M,128] * W[128,128] (+bias) --------------
// 256 threads/block, 64 rows/block, each thread computes 8 rows x 4 cols.
// Inner loop: pure fma.rn.f32x2 on packed b64 operands (2 FMAs/issue).
// WSEL: 0 = g_W1p, 1 = g_W2p, 2 = g_Wqp
// SRC_BUF: 0 = read from param A, 1 = read from g_bufB
// DST: 0 = write g_bufA, 1 = write param C
template <int WSEL, int SRC_BUF, int DST, bool ADD_BIAS>
__global__ void __launch_bounds__(256, 2)
gemm128_kernel(const float* __restrict__ A,
               const float* __restrict__ bias,
               float* __restrict__ C, int M) {
    __shared__ float as[64][DIM];
    const int tx = threadIdx.x & 31;   // col group: cols 4*tx..4*tx+3
    const int ty = threadIdx.x >> 5;   // row group 0..7
    const int row0 = blockIdx.x * 64;

    const float4* A4 = SRC_BUF ? (const float4*)g_bufB : (const float4*)A;
    for (int i = threadIdx.x; i < 64 * 32; i += 256) {
        int r = i >> 5, c = i & 31;
        float4 v = make_float4(0.f, 0.f, 0.f, 0.f);
        if (row0 + r < M) v = A4[(size_t)(row0 + r) * 32 + c];
        ((float4*)as[r])[c] = v;
    }
    __syncthreads();

    // packed accumulators: (even-k partial, odd-k partial) per (row, col)
    unsigned long long acc[8][4];
#pragma unroll
    for (int r = 0; r < 8; r++)
#pragma unroll
        for (int c = 0; c < 4; c++) acc[r][c] = 0ull;

    const float2* Wp = (WSEL == 0) ? g_W1p : (WSEL == 1) ? g_W2p : g_Wqp;
    const ulonglong2* Wp2 = (const ulonglong2*)Wp;
#pragma unroll 4
    for (int k2 = 0; k2 < DIM / 2; k2++) {
        // cols 4tx..4tx+3, each an (even,odd) pair: two 16B loads
        ulonglong2 wA = Wp2[k2 * 64 + tx * 2];      // pairs for cols 4tx, 4tx+1
        ulonglong2 wB = Wp2[k2 * 64 + tx * 2 + 1];  // pairs for cols 4tx+2, 4tx+3
#pragma unroll
        for (int r = 0; r < 8; r++) {
            unsigned long long a2 =
                *(const unsigned long long*)&as[ty * 8 + r][k2 * 2];
            ffma2p(acc[r][0], a2, wA.x);
            ffma2p(acc[r][1], a2, wA.y);
            ffma2p(acc[r][2], a2, wB.x);
            ffma2p(acc[r][3], a2, wB.y);
        }
    }

    float4 bv = make_float4(0.f, 0.f, 0.f, 0.f);
    if (ADD_BIAS) bv = ((const float4*)bias)[tx];
    float4* Cout = DST ? (float4*)C : (float4*)g_bufA;
#pragma unroll
    for (int r = 0; r < 8; r++) {
        int row = row0 + ty * 8 + r;
        if (row < M) {
            float2 p0 = *(float2*)&acc[r][0];
            float2 p1 = *(float2*)&acc[r][1];
            float2 p2 = *(float2*)&acc[r][2];
            float2 p3 = *(float2*)&acc[r][3];
            float4 o;
            o.x = p0.x + p0.y;
            o.y = p1.x + p1.y;
            o.z = p2.x + p2.y;
            o.w = p3.x + p3.y;
            if (ADD_BIAS) { o.x += bv.x; o.y += bv.y; o.z += bv.z; o.w += bv.w; }
            Cout[(size_t)row * 32 + tx] = o;
        }
    }
}

// ---------------- aggregation: out[i] = sum_j norm*h[src] + self + bias -------
// reads g_bufA; DST_BUF: 1 = write g_bufB, 0 = write param out
// block = (32,8): 32 lanes (float4 over 128 feats) x 8 nodes per block
template <int DST_BUF, bool RELU>
__global__ void aggregate_kernel(const float* __restrict__ bias,
                                 float* __restrict__ out) {
    int node = blockIdx.x * 8 + threadIdx.y;
    if (node >= N_NODES) return;
    int lane = threadIdx.x;

    const float4* H4 = (const float4*)g_bufA;
    float di = g_dinv[node];
    float w0 = di * di;
    float4 h = H4[(size_t)node * 32 + lane];
    float4 acc = make_float4(h.x * w0, h.y * w0, h.z * w0, h.w * w0);

    int beg = g_rowptr[node];
    int end = g_rowptr[node + 1];
    int j = beg;
    // 2-wide unroll for MLP against L2 latency
    for (; j + 1 < end; j += 2) {
        int s0 = g_csrsrc[j];
        int s1 = g_csrsrc[j + 1];
        float wa = g_csrw[j];
        float wb = g_csrw[j + 1];
        float4 v0 = H4[(size_t)s0 * 32 + lane];
        float4 v1 = H4[(size_t)s1 * 32 + lane];
        acc.x += v0.x * wa; acc.y += v0.y * wa;
        acc.z += v0.z * wa; acc.w += v0.w * wa;
        acc.x += v1.x * wb; acc.y += v1.y * wb;
        acc.z += v1.z * wb; acc.w += v1.w * wb;
    }
    if (j < end) {
        int s = g_csrsrc[j];
        float w = g_csrw[j];
        float4 v = H4[(size_t)s * 32 + lane];
        acc.x += v.x * w; acc.y += v.y * w;
        acc.z += v.z * w; acc.w += v.w * w;
    }

    float4 bv = ((const float4*)bias)[lane];
    acc.x += bv.x; acc.y += bv.y; acc.z += bv.z; acc.w += bv.w;
    if (RELU) {
        acc.x = fmaxf(acc.x, 0.f);
        acc.y = fmaxf(acc.y, 0.f);
        acc.z = fmaxf(acc.z, 0.f);
        acc.w = fmaxf(acc.w, 0.f);
    }
    float4* O = DST_BUF ? (float4*)g_bufB : (float4*)out;
    O[(size_t)node * 32 + lane] = acc;
}

// ---------------- launch ------------------------------------------------------
extern "C" void kernel_launch(void* const* d_in, const int* in_sizes, int n_in,
                              void* d_out, int out_size) {
    const float* x    = (const float*)d_in[0];
    const int*   ei   = (const int*)d_in[1];
    const float* qemb = (const float*)d_in[2];
    const float* W1   = (const float*)d_in[3];
    const float* b1   = (const float*)d_in[4];
    const float* W2   = (const float*)d_in[5];
    const float* b2   = (const float*)d_in[6];
    const float* Wq   = (const float*)d_in[7];
    const float* bq   = (const float*)d_in[8];

    float* out = (float*)d_out;
    float* out_ques = out;                          // [20000,128]
    float* out_h2   = out + (size_t)20000 * DIM;    // [50000,128]

    // weight packing + graph preprocessing (CSR build, shared by both layers)
    pack_w_kernel<<<(64 * DIM + 255) / 256, 256>>>(W1, W2, Wq);
    init_deg_kernel<<<(N_NODES + 255) / 256, 256>>>();
    count_kernel<<<(N_EDGES + 255) / 256, 256>>>(ei);
    scan_kernel<<<1, 1024>>>();
    scatter_kernel<<<(N_EDGES + 255) / 256, 256>>>(ei);

    const int gblk = 256;
    // layer 1: g_bufA = x @ W1 ; g_bufB = relu(agg(g_bufA) + b1)
    gemm128_kernel<0, 0, 0, false><<<(N_NODES + 63) / 64, gblk>>>(x, nullptr, nullptr, N_NODES);
    aggregate_kernel<1, true><<<(N_NODES + 7) / 8, dim3(32, 8)>>>(b1, nullptr);
    // layer 2: g_bufA = g_bufB @ W2 ; out_h2 = agg(g_bufA) + b2
    gemm128_kernel<1, 1, 0, false><<<(N_NODES + 63) / 64, gblk>>>(nullptr, nullptr, nullptr, N_NODES);
    aggregate_kernel<0, false><<<(N_NODES + 7) / 8, dim3(32, 8)>>>(b2, out_h2);
    // question path: ques = q_emb @ Wq + bq
    gemm128_kernel<2, 0, 1, true><<<(20000 + 63) / 64, gblk>>>(qemb, bq, out_ques, 20000);
}

// round 6
// speedup vs baseline: 1.4860x; 1.3597x over previous
#include <cuda_runtime.h>
#include <cuda_bf16.h>

#define N_NODES 50000
#define N_EDGES 800000
#define DIM 128
#define SCAN_NB ((N_NODES + 255) / 256)   // 196

// ---------------- scratch (static __device__ arrays; no allocation) ----------
__device__ int   g_deg[N_NODES];
__device__ float g_dinv[N_NODES];
__device__ int   g_rowptr[N_NODES + 1];
__device__ int   g_cursor[N_NODES];
__device__ int   g_bsum[256];
__device__ int   g_csrsrc[N_EDGES];
__device__ float g_csrw[N_EDGES];
__device__ float g_bufA[(size_t)N_NODES * DIM];  // GEMM outputs
__device__ float g_bufB[(size_t)N_NODES * DIM];  // h1
// pair-interleaved weights: Wp[k2*DIM + c] = (W[2k2][c], W[2k2+1][c])
__device__ float2 g_W1p[64 * DIM];
__device__ float2 g_W2p[64 * DIM];
__device__ float2 g_Wqp[64 * DIM];

// pure packed fp32x2 FMA: acc(pair) += a(pair) * b(pair), no marshalling movs
__device__ __forceinline__ void ffma2p(unsigned long long& acc,
                                       unsigned long long a,
                                       unsigned long long b) {
    asm("fma.rn.f32x2 %0, %1, %2, %0;" : "+l"(acc) : "l"(a), "l"(b));
}

// ---------------- weight pre-packing ------------------------------------------
__global__ void pack_w_kernel(const float* __restrict__ W1,
                              const float* __restrict__ W2,
                              const float* __restrict__ Wq) {
    int i = blockIdx.x * blockDim.x + threadIdx.x;  // 0 .. 64*128-1
    if (i >= 64 * DIM) return;
    int k2 = i / DIM, c = i % DIM;
    g_W1p[i] = make_float2(W1[(2 * k2) * DIM + c], W1[(2 * k2 + 1) * DIM + c]);
    g_W2p[i] = make_float2(W2[(2 * k2) * DIM + c], W2[(2 * k2 + 1) * DIM + c]);
    g_Wqp[i] = make_float2(Wq[(2 * k2) * DIM + c], Wq[(2 * k2 + 1) * DIM + c]);
}

// ---------------- graph preprocessing ----------------------------------------
__global__ void init_deg_kernel() {
    int i = blockIdx.x * blockDim.x + threadIdx.x;
    if (i < N_NODES) g_deg[i] = 1;  // self-loop
}

// edge_index is int32 (JAX x64-disabled downcasts the declared int64)
__global__ void count_kernel(const int* __restrict__ ei) {
    int e = blockIdx.x * blockDim.x + threadIdx.x;
    if (e < N_EDGES) {
        unsigned d = (unsigned)ei[N_EDGES + e];
        if (d < N_NODES) atomicAdd(&g_deg[d], 1);
    }
}

// ---- 3-phase chip-wide exclusive scan over (deg-1) ---------------------------
__global__ void scan_phase1_kernel() {
    __shared__ int s[256];
    int t = threadIdx.x;
    int i = blockIdx.x * 256 + t;
    int deg = (i < N_NODES) ? g_deg[i] : 1;
    int val = deg - 1;
    s[t] = val;
    __syncthreads();
#pragma unroll
    for (int off = 1; off < 256; off <<= 1) {
        int v = (t >= off) ? s[t - off] : 0;
        __syncthreads();
        s[t] += v;
        __syncthreads();
    }
    if (i < N_NODES) {
        g_rowptr[i] = s[t] - val;   // block-local exclusive prefix
        g_cursor[i] = 0;
        g_dinv[i] = rsqrtf((float)deg);
    }
    if (t == 255) g_bsum[blockIdx.x] = s[255];
}

__global__ void scan_phase2_kernel() {
    __shared__ int s[256];
    int t = threadIdx.x;
    int v = (t < SCAN_NB) ? g_bsum[t] : 0;
    s[t] = v;
    __syncthreads();
#pragma unroll
    for (int off = 1; off < 256; off <<= 1) {
        int u = (t >= off) ? s[t - off] : 0;
        __syncthreads();
        s[t] += u;
        __syncthreads();
    }
    g_bsum[t] = s[t] - v;  // exclusive block offsets
}

__global__ void scan_phase3_kernel() {
    int i = blockIdx.x * 256 + threadIdx.x;
    if (i < N_NODES) g_rowptr[i] += g_bsum[blockIdx.x];
    if (i == 0) g_rowptr[N_NODES] = N_EDGES;  // all dst valid by construction
}

__global__ void scatter_kernel(const int* __restrict__ ei) {
    int e = blockIdx.x * blockDim.x + threadIdx.x;
    if (e < N_EDGES) {
        unsigned src = (unsigned)ei[e];
        unsigned dst = (unsigned)ei[N_EDGES + e];
        if (src < N_NODES && dst < N_NODES) {
            int pos = g_rowptr[dst] + atomicAdd(&g_cursor[dst], 1);
            g_csrsrc[pos] = src;
            g_csrw[pos] = g_dinv[src] * g_dinv[dst];
        }
    }
}

// ---------------- GEMM: C[M,128] = A[M,128] * W[128,128] (+bias) --------------
// 256 threads/block, 64 rows/block, each thread computes 8 rows x 4 cols.
// Inner loop: pure fma.rn.f32x2 on packed b64 operands (2 FMAs/issue).
// WSEL: 0 = g_W1p, 1 = g_W2p, 2 = g_Wqp
// SRC_BUF: 0 = read from param A, 1 = read from g_bufB
// DST: 0 = write g_bufA, 1 = write param C
template <int WSEL, int SRC_BUF, int DST, bool ADD_BIAS>
__global__ void __launch_bounds__(256, 2)
gemm128_kernel(const float* __restrict__ A,
               const float* __restrict__ bias,
               float* __restrict__ C, int M) {
    __shared__ float as[64][DIM];
    const int tx = threadIdx.x & 31;   // col group: cols 4*tx..4*tx+3
    const int ty = threadIdx.x >> 5;   // row group 0..7
    const int row0 = blockIdx.x * 64;

    const float4* A4 = SRC_BUF ? (const float4*)g_bufB : (const float4*)A;
    for (int i = threadIdx.x; i < 64 * 32; i += 256) {
        int r = i >> 5, c = i & 31;
        float4 v = make_float4(0.f, 0.f, 0.f, 0.f);
        if (row0 + r < M) v = A4[(size_t)(row0 + r) * 32 + c];
        ((float4*)as[r])[c] = v;
    }
    __syncthreads();

    // packed accumulators: (even-k partial, odd-k partial) per (row, col)
    unsigned long long acc[8][4];
#pragma unroll
    for (int r = 0; r < 8; r++)
#pragma unroll
        for (int c = 0; c < 4; c++) acc[r][c] = 0ull;

    const float2* Wp = (WSEL == 0) ? g_W1p : (WSEL == 1) ? g_W2p : g_Wqp;
    const ulonglong2* Wp2 = (const ulonglong2*)Wp;
#pragma unroll 4
    for (int k2 = 0; k2 < DIM / 2; k2++) {
        // cols 4tx..4tx+3, each an (even,odd) pair: two 16B loads
        ulonglong2 wA = Wp2[k2 * 64 + tx * 2];      // pairs for cols 4tx, 4tx+1
        ulonglong2 wB = Wp2[k2 * 64 + tx * 2 + 1];  // pairs for cols 4tx+2, 4tx+3
#pragma unroll
        for (int r = 0; r < 8; r++) {
            unsigned long long a2 =
                *(const unsigned long long*)&as[ty * 8 + r][k2 * 2];
            ffma2p(acc[r][0], a2, wA.x);
            ffma2p(acc[r][1], a2, wA.y);
            ffma2p(acc[r][2], a2, wB.x);
            ffma2p(acc[r][3], a2, wB.y);
        }
    }

    float4 bv = make_float4(0.f, 0.f, 0.f, 0.f);
    if (ADD_BIAS) bv = ((const float4*)bias)[tx];
    float4* Cout = DST ? (float4*)C : (float4*)g_bufA;
#pragma unroll
    for (int r = 0; r < 8; r++) {
        int row = row0 + ty * 8 + r;
        if (row < M) {
            float2 p0 = *(float2*)&acc[r][0];
            float2 p1 = *(float2*)&acc[r][1];
            float2 p2 = *(float2*)&acc[r][2];
            float2 p3 = *(float2*)&acc[r][3];
            float4 o;
            o.x = p0.x + p0.y;
            o.y = p1.x + p1.y;
            o.z = p2.x + p2.y;
            o.w = p3.x + p3.y;
            if (ADD_BIAS) { o.x += bv.x; o.y += bv.y; o.z += bv.z; o.w += bv.w; }
            Cout[(size_t)row * 32 + tx] = o;
        }
    }
}

// ---------------- aggregation: out[i] = sum_j norm*h[src] + self + bias -------
// reads g_bufA; DST_BUF: 1 = write g_bufB, 0 = write param out
// block = (32,8): 32 lanes (float4 over 128 feats) x 8 nodes per block
template <int DST_BUF, bool RELU>
__global__ void aggregate_kernel(const float* __restrict__ bias,
                                 float* __restrict__ out) {
    int node = blockIdx.x * 8 + threadIdx.y;
    if (node >= N_NODES) return;
    int lane = threadIdx.x;

    const float4* H4 = (const float4*)g_bufA;
    float di = g_dinv[node];
    float w0 = di * di;
    float4 h = H4[(size_t)node * 32 + lane];
    float4 acc = make_float4(h.x * w0, h.y * w0, h.z * w0, h.w * w0);

    int beg = g_rowptr[node];
    int end = g_rowptr[node + 1];
    int j = beg;
    // 2-wide unroll for MLP against L2 latency
    for (; j + 1 < end; j += 2) {
        int s0 = g_csrsrc[j];
        int s1 = g_csrsrc[j + 1];
        float wa = g_csrw[j];
        float wb = g_csrw[j + 1];
        float4 v0 = H4[(size_t)s0 * 32 + lane];
        float4 v1 = H4[(size_t)s1 * 32 + lane];
        acc.x += v0.x * wa; acc.y += v0.y * wa;
        acc.z += v0.z * wa; acc.w += v0.w * wa;
        acc.x += v1.x * wb; acc.y += v1.y * wb;
        acc.z += v1.z * wb; acc.w += v1.w * wb;
    }
    if (j < end) {
        int s = g_csrsrc[j];
        float w = g_csrw[j];
        float4 v = H4[(size_t)s * 32 + lane];
        acc.x += v.x * w; acc.y += v.y * w;
        acc.z += v.z * w; acc.w += v.w * w;
    }

    float4 bv = ((const float4*)bias)[lane];
    acc.x += bv.x; acc.y += bv.y; acc.z += bv.z; acc.w += bv.w;
    if (RELU) {
        acc.x = fmaxf(acc.x, 0.f);
        acc.y = fmaxf(acc.y, 0.f);
        acc.z = fmaxf(acc.z, 0.f);
        acc.w = fmaxf(acc.w, 0.f);
    }
    float4* O = DST_BUF ? (float4*)g_bufB : (float4*)out;
    O[(size_t)node * 32 + lane] = acc;
}

// ---------------- launch ------------------------------------------------------
extern "C" void kernel_launch(void* const* d_in, const int* in_sizes, int n_in,
                              void* d_out, int out_size) {
    const float* x    = (const float*)d_in[0];
    const int*   ei   = (const int*)d_in[1];
    const float* qemb = (const float*)d_in[2];
    const float* W1   = (const float*)d_in[3];
    const float* b1   = (const float*)d_in[4];
    const float* W2   = (const float*)d_in[5];
    const float* b2   = (const float*)d_in[6];
    const float* Wq   = (const float*)d_in[7];
    const float* bq   = (const float*)d_in[8];

    float* out = (float*)d_out;
    float* out_ques = out;                          // [20000,128]
    float* out_h2   = out + (size_t)20000 * DIM;    // [50000,128]

    // weight packing + graph preprocessing (CSR build, shared by both layers)
    pack_w_kernel<<<(64 * DIM + 255) / 256, 256>>>(W1, W2, Wq);
    init_deg_kernel<<<(N_NODES + 255) / 256, 256>>>();
    count_kernel<<<(N_EDGES + 255) / 256, 256>>>(ei);
    scan_phase1_kernel<<<SCAN_NB, 256>>>();
    scan_phase2_kernel<<<1, 256>>>();
    scan_phase3_kernel<<<SCAN_NB, 256>>>();
    scatter_kernel<<<(N_EDGES + 255) / 256, 256>>>(ei);

    const int gblk = 256;
    // layer 1: g_bufA = x @ W1 ; g_bufB = relu(agg(g_bufA) + b1)
    gemm128_kernel<0, 0, 0, false><<<(N_NODES + 63) / 64, gblk>>>(x, nullptr, nullptr, N_NODES);
    aggregate_kernel<1, true><<<(N_NODES + 7) / 8, dim3(32, 8)>>>(b1, nullptr);
    // layer 2: g_bufA = g_bufB @ W2 ; out_h2 = agg(g_bufA) + b2
    gemm128_kernel<1, 1, 0, false><<<(N_NODES + 63) / 64, gblk>>>(nullptr, nullptr, nullptr, N_NODES);
    aggregate_kernel<0, false><<<(N_NODES + 7) / 8, dim3(32, 8)>>>(b2, out_h2);
    // question path: ques = q_emb @ Wq + bq
    gemm128_kernel<2, 0, 1, true><<<(20000 + 63) / 64, gblk>>>(qemb, bq, out_ques, 20000);
}

// round 9
// speedup vs baseline: 2.0005x; 1.3463x over previous
#include <cuda_runtime.h>
#include <cstdint>

#define N_NODES 50000
#define N_EDGES 800000
#define DIM 128
#define SCAN_NB ((N_NODES + 255) / 256)   // 196

// ---------------- scratch (static __device__ arrays; no allocation) ----------
__device__ int   g_deg[N_NODES];
__device__ float g_dinv[N_NODES];
__device__ int   g_rowptr[N_NODES + 1];
__device__ int   g_cursor[N_NODES];
__device__ int   g_bsum[256];
__device__ int   g_csrsrc[N_EDGES];
__device__ float g_csrw[N_EDGES];
__device__ float g_bufA[(size_t)N_NODES * DIM];  // GEMM outputs
__device__ float g_bufB[(size_t)N_NODES * DIM];  // h1
// B = W in mma fragment order, tf32 hi/lo:
// entry e = (ks*16 + ng)*32 + lane ; float2 = (val@k0, val@k0+4),
// k0 = ks*8 + (lane&3), n = ng*8 + (lane>>2)
__device__ float2 g_Bh[3][8192];
__device__ float2 g_Bl[3][8192];

__device__ __forceinline__ uint32_t tf32_hi_bits(float x) {
    uint32_t r;
    asm("cvt.rna.tf32.f32 %0, %1;" : "=r"(r) : "f"(x));
    return r;
}

// D += A(tf32) * B(tf32), m16n8k8
__device__ __forceinline__ void mma_tf32(float* c, const uint32_t* a,
                                         uint32_t b0, uint32_t b1) {
    asm volatile(
        "mma.sync.aligned.m16n8k8.row.col.f32.tf32.tf32.f32 "
        "{%0,%1,%2,%3}, {%4,%5,%6,%7}, {%8,%9}, {%0,%1,%2,%3};"
        : "+f"(c[0]), "+f"(c[1]), "+f"(c[2]), "+f"(c[3])
        : "r"(a[0]), "r"(a[1]), "r"(a[2]), "r"(a[3]), "r"(b0), "r"(b1));
}

// ---------------- weight pre-packing: fragment-ordered tf32 hi/lo -------------
__global__ void pack_w_kernel(const float* __restrict__ W1,
                              const float* __restrict__ W2,
                              const float* __restrict__ Wq) {
    int i = blockIdx.x * blockDim.x + threadIdx.x;
    if (i >= 3 * 8192) return;
    int w = i / 8192, e = i % 8192;
    int ks = e / 512, rem = e % 512;
    int ng = rem / 32, lane = rem % 32;
    int k0 = ks * 8 + (lane & 3);
    int n = ng * 8 + (lane >> 2);
    const float* Ws = (w == 0) ? W1 : (w == 1) ? W2 : Wq;
    float v0 = Ws[k0 * DIM + n];
    float v1 = Ws[(k0 + 4) * DIM + n];
    uint32_t h0 = tf32_hi_bits(v0), h1 = tf32_hi_bits(v1);
    uint32_t l0 = tf32_hi_bits(v0 - __uint_as_float(h0));
    uint32_t l1 = tf32_hi_bits(v1 - __uint_as_float(h1));
    g_Bh[w][e] = make_float2(__uint_as_float(h0), __uint_as_float(h1));
    g_Bl[w][e] = make_float2(__uint_as_float(l0), __uint_as_float(l1));
}

// ---------------- graph preprocessing ----------------------------------------
__global__ void init_deg_kernel() {
    int i = blockIdx.x * blockDim.x + threadIdx.x;
    if (i < N_NODES) g_deg[i] = 1;  // self-loop
}

// edge_index is int32 (JAX x64-disabled downcasts the declared int64)
__global__ void count_kernel(const int* __restrict__ ei) {
    int e = blockIdx.x * blockDim.x + threadIdx.x;
    if (e < N_EDGES) {
        unsigned d = (unsigned)ei[N_EDGES + e];
        if (d < N_NODES) atomicAdd(&g_deg[d], 1);
    }
}

__global__ void scan_phase1_kernel() {
    __shared__ int s[256];
    int t = threadIdx.x;
    int i = blockIdx.x * 256 + t;
    int deg = (i < N_NODES) ? g_deg[i] : 1;
    int val = deg - 1;
    s[t] = val;
    __syncthreads();
#pragma unroll
    for (int off = 1; off < 256; off <<= 1) {
        int v = (t >= off) ? s[t - off] : 0;
        __syncthreads();
        s[t] += v;
        __syncthreads();
    }
    if (i < N_NODES) {
        g_rowptr[i] = s[t] - val;
        g_cursor[i] = 0;
        g_dinv[i] = rsqrtf((float)deg);
    }
    if (t == 255) g_bsum[blockIdx.x] = s[255];
}

__global__ void scan_phase2_kernel() {
    __shared__ int s[256];
    int t = threadIdx.x;
    int v = (t < SCAN_NB) ? g_bsum[t] : 0;
    s[t] = v;
    __syncthreads();
#pragma unroll
    for (int off = 1; off < 256; off <<= 1) {
        int u = (t >= off) ? s[t - off] : 0;
        __syncthreads();
        s[t] += u;
        __syncthreads();
    }
    g_bsum[t] = s[t] - v;
}

__global__ void scan_phase3_kernel() {
    int i = blockIdx.x * 256 + threadIdx.x;
    if (i < N_NODES) g_rowptr[i] += g_bsum[blockIdx.x];
    if (i == 0) g_rowptr[N_NODES] = N_EDGES;
}

__global__ void scatter_kernel(const int* __restrict__ ei) {
    int e = blockIdx.x * blockDim.x + threadIdx.x;
    if (e < N_EDGES) {
        unsigned src = (unsigned)ei[e];
        unsigned dst = (unsigned)ei[N_EDGES + e];
        if (src < N_NODES && dst < N_NODES) {
            int pos = g_rowptr[dst] + atomicAdd(&g_cursor[dst], 1);
            g_csrsrc[pos] = src;
            g_csrw[pos] = g_dinv[src] * g_dinv[dst];
        }
    }
}

// ---------------- GEMM via mma.sync tf32 (3xTF32): C = A @ W (+bias) ----------
// block: 256 threads = 8 warps, tile 64 rows x 128 cols.
// warp grid: 2 (M) x 4 (N); warp tile 32x32 = 2 mtiles x 4 ntiles of m16n8k8.
// WSEL: weight set; SRC_BUF: 1 = read g_bufB; DST: 1 = write param C
template <int WSEL, int SRC_BUF, int DST, bool ADD_BIAS>
__global__ void __launch_bounds__(256)
gemm_mma_kernel(const float* __restrict__ A,
                const float* __restrict__ bias,
                float* __restrict__ C, int M) {
    __shared__ float sA[64][132];   // pad 132 -> conflict-free fragment LDS

    const int tid = threadIdx.x;
    const int wid = tid >> 5;
    const int lane = tid & 31;
    const int gid = lane >> 2;      // group id (0..7)
    const int tid4 = lane & 3;      // thread-in-group (0..3)
    const int warpM = (wid & 1) * 32;
    const int warpNg = wid >> 1;    // 0..3 (n-offset = warpNg*32)
    const int row0 = blockIdx.x * 64;

    // load A tile (64x128) -> SMEM
    const float* Abase = SRC_BUF ? g_bufB : A;
    const float4* A4 = (const float4*)Abase;
#pragma unroll
    for (int t = 0; t < 8; t++) {
        int idx = tid + t * 256;          // 0..2047
        int r = idx >> 5, c = idx & 31;
        float4 v = make_float4(0.f, 0.f, 0.f, 0.f);
        if (row0 + r < M) v = A4[(size_t)(row0 + r) * 32 + c];
        *(float4*)&sA[r][c * 4] = v;
    }
    __syncthreads();

    float acc[2][4][4];
#pragma unroll
    for (int mt = 0; mt < 2; mt++)
#pragma unroll
        for (int nt = 0; nt < 4; nt++)
#pragma unroll
            for (int k = 0; k < 4; k++) acc[mt][nt][k] = 0.f;

#pragma unroll 2
    for (int ks = 0; ks < 16; ks++) {
        // A fragments (hi/lo) for both mtiles
        uint32_t ah[2][4], al[2][4];
#pragma unroll
        for (int mt = 0; mt < 2; mt++) {
            int rb = warpM + mt * 16;
            int col = ks * 8 + tid4;
            float v0 = sA[rb + gid][col];
            float v1 = sA[rb + gid + 8][col];
            float v2 = sA[rb + gid][col + 4];
            float v3 = sA[rb + gid + 8][col + 4];
            ah[mt][0] = tf32_hi_bits(v0);
            ah[mt][1] = tf32_hi_bits(v1);
            ah[mt][2] = tf32_hi_bits(v2);
            ah[mt][3] = tf32_hi_bits(v3);
            al[mt][0] = tf32_hi_bits(v0 - __uint_as_float(ah[mt][0]));
            al[mt][1] = tf32_hi_bits(v1 - __uint_as_float(ah[mt][1]));
            al[mt][2] = tf32_hi_bits(v2 - __uint_as_float(ah[mt][2]));
            al[mt][3] = tf32_hi_bits(v3 - __uint_as_float(ah[mt][3]));
        }
#pragma unroll
        for (int nt = 0; nt < 4; nt++) {
            int ng = warpNg * 4 + nt;
            float2 bh = __ldg(&g_Bh[WSEL][(ks * 16 + ng) * 32 + lane]);
            float2 bl = __ldg(&g_Bl[WSEL][(ks * 16 + ng) * 32 + lane]);
            uint32_t bh0 = __float_as_uint(bh.x), bh1 = __float_as_uint(bh.y);
            uint32_t bl0 = __float_as_uint(bl.x), bl1 = __float_as_uint(bl.y);
#pragma unroll
            for (int mt = 0; mt < 2; mt++) {
                mma_tf32(acc[mt][nt], ah[mt], bh0, bh1);  // Ah*Bh
                mma_tf32(acc[mt][nt], al[mt], bh0, bh1);  // Al*Bh
                mma_tf32(acc[mt][nt], ah[mt], bl0, bl1);  // Ah*Bl
            }
        }
    }

    // epilogue
    float* Cout = DST ? C : g_bufA;
#pragma unroll
    for (int mt = 0; mt < 2; mt++) {
#pragma unroll
        for (int nt = 0; nt < 4; nt++) {
            int col = warpNg * 32 + nt * 8 + tid4 * 2;
            float bx = 0.f, by = 0.f;
            if (ADD_BIAS) {
                float2 bv = ((const float2*)bias)[col >> 1];
                bx = bv.x; by = bv.y;
            }
            int r0 = row0 + warpM + mt * 16 + gid;
            if (r0 < M) {
                float2 o = make_float2(acc[mt][nt][0] + bx, acc[mt][nt][1] + by);
                *(float2*)&Cout[(size_t)r0 * DIM + col] = o;
            }
            if (r0 + 8 < M) {
                float2 o = make_float2(acc[mt][nt][2] + bx, acc[mt][nt][3] + by);
                *(float2*)&Cout[(size_t)(r0 + 8) * DIM + col] = o;
            }
        }
    }
}

// ---------------- aggregation: out[i] = sum_j norm*h[src] + self + bias -------
template <int DST_BUF, bool RELU>
__global__ void aggregate_kernel(const float* __restrict__ bias,
                                 float* __restrict__ out) {
    int node = blockIdx.x * 8 + threadIdx.y;
    if (node >= N_NODES) return;
    int lane = threadIdx.x;

    const float4* H4 = (const float4*)g_bufA;
    float di = g_dinv[node];
    float w0 = di * di;
    float4 h = H4[(size_t)node * 32 + lane];
    float4 acc = make_float4(h.x * w0, h.y * w0, h.z * w0, h.w * w0);

    int beg = g_rowptr[node];
    int end = g_rowptr[node + 1];
    int j = beg;
    for (; j + 1 < end; j += 2) {
        int s0 = g_csrsrc[j];
        int s1 = g_csrsrc[j + 1];
        float wa = g_csrw[j];
        float wb = g_csrw[j + 1];
        float4 v0 = H4[(size_t)s0 * 32 + lane];
        float4 v1 = H4[(size_t)s1 * 32 + lane];
        acc.x += v0.x * wa; acc.y += v0.y * wa;
        acc.z += v0.z * wa; acc.w += v0.w * wa;
        acc.x += v1.x * wb; acc.y += v1.y * wb;
        acc.z += v1.z * wb; acc.w += v1.w * wb;
    }
    if (j < end) {
        int s = g_csrsrc[j];
        float w = g_csrw[j];
        float4 v = H4[(size_t)s * 32 + lane];
        acc.x += v.x * w; acc.y += v.y * w;
        acc.z += v.z * w; acc.w += v.w * w;
    }

    float4 bv = ((const float4*)bias)[lane];
    acc.x += bv.x; acc.y += bv.y; acc.z += bv.z; acc.w += bv.w;
    if (RELU) {
        acc.x = fmaxf(acc.x, 0.f);
        acc.y = fmaxf(acc.y, 0.f);
        acc.z = fmaxf(acc.z, 0.f);
        acc.w = fmaxf(acc.w, 0.f);
    }
    float4* O = DST_BUF ? (float4*)g_bufB : (float4*)out;
    O[(size_t)node * 32 + lane] = acc;
}

// ---------------- launch ------------------------------------------------------
extern "C" void kernel_launch(void* const* d_in, const int* in_sizes, int n_in,
                              void* d_out, int out_size) {
    const float* x    = (const float*)d_in[0];
    const int*   ei   = (const int*)d_in[1];
    const float* qemb = (const float*)d_in[2];
    const float* W1   = (const float*)d_in[3];
    const float* b1   = (const float*)d_in[4];
    const float* W2   = (const float*)d_in[5];
    const float* b2   = (const float*)d_in[6];
    const float* Wq   = (const float*)d_in[7];
    const float* bq   = (const float*)d_in[8];

    float* out = (float*)d_out;
    float* out_ques = out;                          // [20000,128]
    float* out_h2   = out + (size_t)20000 * DIM;    // [50000,128]

    // weight packing + graph preprocessing
    pack_w_kernel<<<(3 * 8192 + 255) / 256, 256>>>(W1, W2, Wq);
    init_deg_kernel<<<(N_NODES + 255) / 256, 256>>>();
    count_kernel<<<(N_EDGES + 255) / 256, 256>>>(ei);
    scan_phase1_kernel<<<SCAN_NB, 256>>>();
    scan_phase2_kernel<<<1, 256>>>();
    scan_phase3_kernel<<<SCAN_NB, 256>>>();
    scatter_kernel<<<(N_EDGES + 255) / 256, 256>>>(ei);

    // layer 1: g_bufA = x @ W1 ; g_bufB = relu(agg(g_bufA) + b1)
    gemm_mma_kernel<0, 0, 0, false><<<(N_NODES + 63) / 64, 256>>>(x, nullptr, nullptr, N_NODES);
    aggregate_kernel<1, true><<<(N_NODES + 7) / 8, dim3(32, 8)>>>(b1, nullptr);
    // layer 2: g_bufA = g_bufB @ W2 ; out_h2 = agg(g_bufA) + b2
    gemm_mma_kernel<1, 1, 0, false><<<(N_NODES + 63) / 64, 256>>>(nullptr, nullptr, nullptr, N_NODES);
    aggregate_kernel<0, false><<<(N_NODES + 7) / 8, dim3(32, 8)>>>(b2, out_h2);
    // question path: ques = q_emb @ Wq + bq
    gemm_mma_kernel<2, 0, 1, true><<<(20000 + 63) / 64, 256>>>(qemb, bq, out_ques, 20000);
}